// round 6
// baseline (speedup 1.0000x reference)
#include <cuda_runtime.h>

// Problem constants: B=4, S=2048, D=1024, H=16, HD=64
namespace {
constexpr int B_  = 4;
constexpr int S_  = 2048;
constexpr int D_  = 1024;
constexpr int NH_ = 16;
constexpr int HD_ = 64;
constexpr int MROWS = B_ * S_;              // 8192
constexpr int PART  = B_ * NH_ * S_ * HD_;  // 8,388,608 elems per Q/K/V part
constexpr int FLASH_SMEM = (3 * 64 * 68 + 64 * 64) * 4;  // 68,608 bytes
}

// Scratch (static device globals: allowed; runtime allocation is not)
__device__ float g_qkv[3 * PART];       // [3][B,H,S,HD]
__device__ float g_att[B_ * S_ * D_];   // [B,S,H,HD] == [B,S,D]

// ---------------------------------------------------------------------------
// Tiled SGEMM: C[M,N] = A[M,K] @ W[K,N] + bias[N]
//   64x64 block tile, BK=16, 4x4 micro-tile, 256 threads.
//   MODE 0: A = Ain (x), epilogue scatters into g_qkv [3][B,H,S,HD]
//   MODE 1: A = g_att, epilogue writes Cout[M,N] directly
// ---------------------------------------------------------------------------
template <int MODE>
__global__ void __launch_bounds__(256) sgemm_kernel(
    const float* __restrict__ Ain, const float* __restrict__ Wm,
    const float* __restrict__ bias, float* __restrict__ Cout,
    int K, int N)
{
    __shared__ float As[16][68];  // A tile transposed: As[k][row], padded
    __shared__ float Bs[16][64];  // B tile: Bs[k][col]

    const int tid = threadIdx.x;
    const int ty = tid >> 4;          // 0..15 -> output rows ty*4..+3
    const int tx = tid & 15;          // 0..15 -> output cols tx*4..+3
    const int m0 = blockIdx.y << 6;
    const int n0 = blockIdx.x << 6;

    const float* A = (MODE == 0) ? Ain : g_att;

    // global->smem load assignments (A tile is 64x16 = 1024 floats = 256 x float4)
    const int arow = tid >> 2;        // 0..63  (A tile row)
    const int ac4  = (tid & 3) << 2;  // 0,4,8,12 (A tile col group)
    const int bkk  = tid >> 4;        // 0..15  (B tile k-row)
    const int bc4  = (tid & 15) << 2; // 0..60  (B tile col group)

    float acc[4][4];
#pragma unroll
    for (int i = 0; i < 4; ++i)
#pragma unroll
        for (int j = 0; j < 4; ++j) acc[i][j] = 0.f;

    const float* aptr = A + (m0 + arow) * K + ac4;
    const float* bptr = Wm + bkk * N + n0 + bc4;

    for (int k0 = 0; k0 < K; k0 += 16) {
        float4 av = *reinterpret_cast<const float4*>(aptr + k0);
        float4 bv = *reinterpret_cast<const float4*>(bptr + k0 * N);
        As[ac4 + 0][arow] = av.x;
        As[ac4 + 1][arow] = av.y;
        As[ac4 + 2][arow] = av.z;
        As[ac4 + 3][arow] = av.w;
        *reinterpret_cast<float4*>(&Bs[bkk][bc4]) = bv;
        __syncthreads();
#pragma unroll
        for (int k = 0; k < 16; ++k) {
            float4 a4 = *reinterpret_cast<const float4*>(&As[k][ty << 2]);
            float4 b4 = *reinterpret_cast<const float4*>(&Bs[k][tx << 2]);
            float ar[4] = {a4.x, a4.y, a4.z, a4.w};
            float br[4] = {b4.x, b4.y, b4.z, b4.w};
#pragma unroll
            for (int i = 0; i < 4; ++i)
#pragma unroll
                for (int j = 0; j < 4; ++j)
                    acc[i][j] = fmaf(ar[i], br[j], acc[i][j]);
        }
        __syncthreads();
    }

    const int cn = n0 + (tx << 2);
    const float4 bias4 = *reinterpret_cast<const float4*>(bias + cn);

    if (MODE == 0) {
        // scatter into g_qkv [part][b][h][s][hd]; tile cols are 64-aligned so
        // all 4 cols share one (part, h) and are contiguous in hd.
        const int part = cn >> 10;
        const int rem  = cn & 1023;
        const int h    = rem >> 6;
        const int hd0  = rem & 63;
        float* dst_base = g_qkv + part * PART;
#pragma unroll
        for (int i = 0; i < 4; ++i) {
            const int m  = m0 + (ty << 2) + i;
            const int bb = m >> 11;    // m / S_
            const int ss = m & 2047;   // m % S_
            float4 o;
            o.x = acc[i][0] + bias4.x;
            o.y = acc[i][1] + bias4.y;
            o.z = acc[i][2] + bias4.z;
            o.w = acc[i][3] + bias4.w;
            *reinterpret_cast<float4*>(
                dst_base + ((bb * NH_ + h) * S_ + ss) * HD_ + hd0) = o;
        }
    } else {
#pragma unroll
        for (int i = 0; i < 4; ++i) {
            const int m = m0 + (ty << 2) + i;
            float4 o;
            o.x = acc[i][0] + bias4.x;
            o.y = acc[i][1] + bias4.y;
            o.z = acc[i][2] + bias4.z;
            o.w = acc[i][3] + bias4.w;
            *reinterpret_cast<float4*>(Cout + m * N + cn) = o;
        }
    }
}

// ---------------------------------------------------------------------------
// Flash attention, fp32, HD=64.
//   Grid: (S/64 query tiles, B*H). 256 threads, 4x4 micro-tiles.
//   Per key tile (64): scores GEMM, online softmax, PV GEMM.
//   NOTE: Q/K/V tiles are 64x64 = 4096 floats; with 256 threads each thread
//   must load FOUR float4s per tensor (chunked over the 64 columns).
// ---------------------------------------------------------------------------
__global__ void __launch_bounds__(256) flash_kernel()
{
    extern __shared__ float sm[];
    float (*Qt)[68] = reinterpret_cast<float(*)[68]>(sm);                 // [d][i]
    float (*Kt)[68] = reinterpret_cast<float(*)[68]>(sm + 64 * 68);       // [d][j]
    float (*Pt)[68] = reinterpret_cast<float(*)[68]>(sm + 2 * 64 * 68);   // [j][i]
    float (*Vs)[64] = reinterpret_cast<float(*)[64]>(sm + 3 * 64 * 68);   // [j][c]

    const int tid = threadIdx.x;
    const int ty = tid >> 4;   // query-row group (rows ty*4..+3)
    const int tx = tid & 15;   // key-col / out-col group (cols tx*4..+3)
    const int bh = blockIdx.y;          // b*NH + h
    const int q0 = blockIdx.x << 6;

    const float* Qg = g_qkv + bh * (S_ * HD_);
    const float* Kg = g_qkv + PART + bh * (S_ * HD_);
    const float* Vg = g_qkv + 2 * PART + bh * (S_ * HD_);

    const int lrow = tid >> 2;        // 0..63
    const int lc4  = (tid & 3) << 2;  // 0,4,8,12 (base column; +16,+32,+48 chunks)

    // Load Q tile transposed, pre-scaled by HD^-0.5 = 0.125.
    // Full 64 dims: 4 chunks of 16 columns each.
#pragma unroll
    for (int c = 0; c < 64; c += 16) {
        float4 qv = *reinterpret_cast<const float4*>(
            Qg + (q0 + lrow) * HD_ + lc4 + c);
        Qt[lc4 + c + 0][lrow] = qv.x * 0.125f;
        Qt[lc4 + c + 1][lrow] = qv.y * 0.125f;
        Qt[lc4 + c + 2][lrow] = qv.z * 0.125f;
        Qt[lc4 + c + 3][lrow] = qv.w * 0.125f;
    }

    float m_r[4], l_r[4], O[4][4];
#pragma unroll
    for (int a = 0; a < 4; ++a) {
        m_r[a] = -1e30f;
        l_r[a] = 0.f;
#pragma unroll
        for (int c = 0; c < 4; ++c) O[a][c] = 0.f;
    }

    for (int kt = 0; kt < S_; kt += 64) {
        __syncthreads();  // previous tile's Pt/Vs readers done before overwrite
        // Load K tile transposed and V tile, full 64 dims (4 chunks).
#pragma unroll
        for (int c = 0; c < 64; c += 16) {
            float4 kv = *reinterpret_cast<const float4*>(
                Kg + (kt + lrow) * HD_ + lc4 + c);
            Kt[lc4 + c + 0][lrow] = kv.x;
            Kt[lc4 + c + 1][lrow] = kv.y;
            Kt[lc4 + c + 2][lrow] = kv.z;
            Kt[lc4 + c + 3][lrow] = kv.w;
            float4 vv = *reinterpret_cast<const float4*>(
                Vg + (kt + lrow) * HD_ + lc4 + c);
            *reinterpret_cast<float4*>(&Vs[lrow][lc4 + c]) = vv;
        }
        __syncthreads();

        // scores: sc[a][j] = sum_d Q[qrow][d] * K[kcol][d]   (Q pre-scaled)
        float sc[4][4];
#pragma unroll
        for (int a = 0; a < 4; ++a)
#pragma unroll
            for (int j = 0; j < 4; ++j) sc[a][j] = 0.f;
#pragma unroll
        for (int d = 0; d < 64; ++d) {
            float4 a4 = *reinterpret_cast<const float4*>(&Qt[d][ty << 2]);
            float4 b4 = *reinterpret_cast<const float4*>(&Kt[d][tx << 2]);
            float ar[4] = {a4.x, a4.y, a4.z, a4.w};
            float br[4] = {b4.x, b4.y, b4.z, b4.w};
#pragma unroll
            for (int a = 0; a < 4; ++a)
#pragma unroll
                for (int j = 0; j < 4; ++j)
                    sc[a][j] = fmaf(ar[a], br[j], sc[a][j]);
        }

        // online softmax: row = query row; reduce over 16 tx lanes
        // (lane = (ty&1)*16 + tx, so xor 1/2/4/8 stays within the tx group)
#pragma unroll
        for (int a = 0; a < 4; ++a) {
            float mx = fmaxf(fmaxf(sc[a][0], sc[a][1]), fmaxf(sc[a][2], sc[a][3]));
#pragma unroll
            for (int off = 8; off > 0; off >>= 1)
                mx = fmaxf(mx, __shfl_xor_sync(0xffffffffu, mx, off));
            const float nm = fmaxf(m_r[a], mx);
            const float corr = __expf(m_r[a] - nm);
            m_r[a] = nm;
            float rs = 0.f;
#pragma unroll
            for (int j = 0; j < 4; ++j) {
                sc[a][j] = __expf(sc[a][j] - nm);
                rs += sc[a][j];
            }
#pragma unroll
            for (int off = 8; off > 0; off >>= 1)
                rs += __shfl_xor_sync(0xffffffffu, rs, off);
            l_r[a] = l_r[a] * corr + rs;
#pragma unroll
            for (int j = 0; j < 4; ++j) O[a][j] *= corr;
        }

        // stage P transposed: Pt[j][i] = P[i][j]
#pragma unroll
        for (int a = 0; a < 4; ++a)
#pragma unroll
            for (int j = 0; j < 4; ++j)
                Pt[(tx << 2) + j][(ty << 2) + a] = sc[a][j];
        __syncthreads();

        // O[a][c] += sum_j P[qrow][j] * V[j][c]
#pragma unroll
        for (int j = 0; j < 64; ++j) {
            float4 p4 = *reinterpret_cast<const float4*>(&Pt[j][ty << 2]);
            float4 v4 = *reinterpret_cast<const float4*>(&Vs[j][tx << 2]);
            float pr[4] = {p4.x, p4.y, p4.z, p4.w};
            float vr[4] = {v4.x, v4.y, v4.z, v4.w};
#pragma unroll
            for (int a = 0; a < 4; ++a)
#pragma unroll
                for (int c = 0; c < 4; ++c)
                    O[a][c] = fmaf(pr[a], vr[c], O[a][c]);
        }
    }

    // epilogue: normalize, write to g_att [B,S,H,HD]
    const int bb = bh >> 4;
    const int h  = bh & 15;
#pragma unroll
    for (int a = 0; a < 4; ++a) {
        const float inv = 1.f / l_r[a];
        const int row = q0 + (ty << 2) + a;
        float4 o;
        o.x = O[a][0] * inv;
        o.y = O[a][1] * inv;
        o.z = O[a][2] * inv;
        o.w = O[a][3] * inv;
        *reinterpret_cast<float4*>(
            g_att + ((bb * S_ + row) * NH_ + h) * HD_ + (tx << 2)) = o;
    }
}

// ---------------------------------------------------------------------------
extern "C" void kernel_launch(void* const* d_in, const int* in_sizes, int n_in,
                              void* d_out, int out_size)
{
    (void)in_sizes; (void)n_in; (void)out_size;
    const float* x     = (const float*)d_in[0];
    const float* w_qkv = (const float*)d_in[1];
    const float* b_qkv = (const float*)d_in[2];
    const float* w_out = (const float*)d_in[3];
    const float* b_out = (const float*)d_in[4];
    float* out = (float*)d_out;

    // idempotent, capture-safe (not a stream op, not an allocation)
    cudaFuncSetAttribute(flash_kernel,
                         cudaFuncAttributeMaxDynamicSharedMemorySize, FLASH_SMEM);

    // 1) QKV GEMM + bias + scatter: [8192,1024] @ [1024,3072]
    sgemm_kernel<0><<<dim3((3 * D_) / 64, MROWS / 64), 256>>>(
        x, w_qkv, b_qkv, nullptr, D_, 3 * D_);

    // 2) Flash attention over all (b,h) and query tiles
    flash_kernel<<<dim3(S_ / 64, B_ * NH_), 256, FLASH_SMEM>>>();

    // 3) Output projection: [8192,1024] @ [1024,1024] + bias -> d_out
    sgemm_kernel<1><<<dim3(D_ / 64, MROWS / 64), 256>>>(
        nullptr, w_out, b_out, out, D_, D_);
}

// round 7
// speedup vs baseline: 2.8661x; 2.8661x over previous
#include <cuda_runtime.h>
#include <cstdint>

// Problem constants: B=4, S=2048, D=1024, H=16, HD=64
namespace {
constexpr int B_  = 4;
constexpr int S_  = 2048;
constexpr int D_  = 1024;
constexpr int NH_ = 16;
constexpr int HD_ = 64;
constexpr int MROWS = B_ * S_;              // 8192
constexpr int PART  = B_ * NH_ * S_ * HD_;  // 8,388,608 elems per Q/K/V part
// Flash smem: Qs (reused as Ps), Ks, Vs -- each [64][68] floats
constexpr int FLASH_SMEM = 3 * 64 * 68 * 4;  // 52,224 bytes
}

// Scratch (static device globals: allowed; runtime allocation is not)
__device__ float g_qkv[3 * PART];       // [3][B,H,S,HD]
__device__ float g_att[B_ * S_ * D_];   // [B,S,H,HD] == [B,S,D]

// ---------------------------------------------------------------------------
// helpers: tf32 convert (round-to-nearest) + m16n8k8 tf32 MMA
// ---------------------------------------------------------------------------
__device__ __forceinline__ float tf32r(float x) {
    uint32_t u;
    asm("cvt.rna.tf32.f32 %0, %1;" : "=r"(u) : "f"(x));
    return __uint_as_float(u);
}

__device__ __forceinline__ void mma_tf32(float c[4], const uint32_t a[4],
                                         uint32_t b0, uint32_t b1) {
    asm volatile(
        "mma.sync.aligned.m16n8k8.row.col.f32.tf32.tf32.f32 "
        "{%0,%1,%2,%3}, {%4,%5,%6,%7}, {%8,%9}, {%0,%1,%2,%3};"
        : "+f"(c[0]), "+f"(c[1]), "+f"(c[2]), "+f"(c[3])
        : "r"(a[0]), "r"(a[1]), "r"(a[2]), "r"(a[3]), "r"(b0), "r"(b1));
}

// ---------------------------------------------------------------------------
// TF32 tensor-core GEMM: C[M,N] = A[M,K] @ W[K,N] + bias[N]
//   128x128 block tile, BK=16, 256 threads (8 warps in 2x4),
//   each warp 64x32 via 4x4 grid of m16n8k8.
//   MODE 0: A = Ain (x), epilogue scatters into g_qkv [3][B,H,S,HD]
//   MODE 1: A = g_att, epilogue writes Cout[M,N] directly
// ---------------------------------------------------------------------------
template <int MODE>
__global__ void __launch_bounds__(256) gemm_tc(
    const float* __restrict__ Ain, const float* __restrict__ Wm,
    const float* __restrict__ bias, float* __restrict__ Cout,
    int K, int N)
{
    __shared__ float As[128][20];   // pad 16->20: conflict-free A frag loads
    __shared__ float Bs[16][132];   // pad 128->132: <=2-way on B frag loads

    const int tid  = threadIdx.x;
    const int wid  = tid >> 5;
    const int lane = tid & 31;
    const int g    = lane >> 2;   // group id (row within fragment)
    const int tg   = lane & 3;    // thread-in-group (col within fragment)
    const int warp_m = wid >> 2;  // 0..1 -> m offset *64
    const int warp_n = wid & 3;   // 0..3 -> n offset *32
    const int m0 = blockIdx.y << 7;
    const int n0 = blockIdx.x << 7;

    const float* A = (MODE == 0) ? Ain : g_att;

    float c[4][4][4];
#pragma unroll
    for (int mt = 0; mt < 4; ++mt)
#pragma unroll
        for (int nt = 0; nt < 4; ++nt)
#pragma unroll
            for (int i = 0; i < 4; ++i) c[mt][nt][i] = 0.f;

    for (int k0 = 0; k0 < K; k0 += 16) {
        // stage A: 128x16 floats = 512 float4 over 256 threads
#pragma unroll
        for (int i = tid; i < 512; i += 256) {
            const int r  = i >> 2;
            const int c4 = (i & 3) << 2;
            float4 v = *reinterpret_cast<const float4*>(
                A + (m0 + r) * K + k0 + c4);
            As[r][c4 + 0] = tf32r(v.x);
            As[r][c4 + 1] = tf32r(v.y);
            As[r][c4 + 2] = tf32r(v.z);
            As[r][c4 + 3] = tf32r(v.w);
        }
        // stage B: 16x128 floats = 512 float4
#pragma unroll
        for (int i = tid; i < 512; i += 256) {
            const int r  = i >> 5;
            const int c4 = (i & 31) << 2;
            float4 v = *reinterpret_cast<const float4*>(
                Wm + (k0 + r) * N + n0 + c4);
            Bs[r][c4 + 0] = tf32r(v.x);
            Bs[r][c4 + 1] = tf32r(v.y);
            Bs[r][c4 + 2] = tf32r(v.z);
            Bs[r][c4 + 3] = tf32r(v.w);
        }
        __syncthreads();

#pragma unroll
        for (int kk = 0; kk < 16; kk += 8) {
            uint32_t a[4][4], b[4][2];
#pragma unroll
            for (int mt = 0; mt < 4; ++mt) {
                const int r = (warp_m << 6) + (mt << 4) + g;
                a[mt][0] = __float_as_uint(As[r    ][kk + tg    ]);
                a[mt][1] = __float_as_uint(As[r + 8][kk + tg    ]);
                a[mt][2] = __float_as_uint(As[r    ][kk + tg + 4]);
                a[mt][3] = __float_as_uint(As[r + 8][kk + tg + 4]);
            }
#pragma unroll
            for (int nt = 0; nt < 4; ++nt) {
                const int cn = (warp_n << 5) + (nt << 3) + g;
                b[nt][0] = __float_as_uint(Bs[kk + tg    ][cn]);
                b[nt][1] = __float_as_uint(Bs[kk + tg + 4][cn]);
            }
#pragma unroll
            for (int mt = 0; mt < 4; ++mt)
#pragma unroll
                for (int nt = 0; nt < 4; ++nt)
                    mma_tf32(c[mt][nt], a[mt], b[nt][0], b[nt][1]);
        }
        __syncthreads();
    }

    // epilogue: C fragment (row=g/g+8, cols 2*tg, 2*tg+1) + bias
#pragma unroll
    for (int nt = 0; nt < 4; ++nt) {
        const int col = n0 + (warp_n << 5) + (nt << 3) + (tg << 1);
        const float2 b2 = *reinterpret_cast<const float2*>(bias + col);
#pragma unroll
        for (int mt = 0; mt < 4; ++mt) {
            const int r_lo = m0 + (warp_m << 6) + (mt << 4) + g;
            float2 vlo, vhi;
            vlo.x = c[mt][nt][0] + b2.x;
            vlo.y = c[mt][nt][1] + b2.y;
            vhi.x = c[mt][nt][2] + b2.x;
            vhi.y = c[mt][nt][3] + b2.y;
            if (MODE == 0) {
                const int part = col >> 10;
                const int rem  = col & 1023;
                const int h    = rem >> 6;
                const int hd0  = rem & 63;
                float* dst = g_qkv + part * PART;
                {
                    const int m  = r_lo;
                    const int bb = m >> 11, ss = m & 2047;
                    *reinterpret_cast<float2*>(
                        dst + ((bb * NH_ + h) * S_ + ss) * HD_ + hd0) = vlo;
                }
                {
                    const int m  = r_lo + 8;
                    const int bb = m >> 11, ss = m & 2047;
                    *reinterpret_cast<float2*>(
                        dst + ((bb * NH_ + h) * S_ + ss) * HD_ + hd0) = vhi;
                }
            } else {
                *reinterpret_cast<float2*>(Cout + r_lo * N + col) = vlo;
                *reinterpret_cast<float2*>(Cout + (r_lo + 8) * N + col) = vhi;
            }
        }
    }
}

// ---------------------------------------------------------------------------
// Flash attention, tf32 tensor cores, HD=64.
//   Grid: (S/64 query tiles, B*H). 128 threads = 4 warps, warp w owns
//   query rows [w*16, w*16+16). Scores and PV both via m16n8k8 tf32 MMA.
//   Q kept as persistent A-fragments in registers (pre-scaled by 0.125).
//   P restaged through smem (reusing the Q staging buffer) to convert
//   C-fragment layout -> A-fragment layout.
// ---------------------------------------------------------------------------
__global__ void __launch_bounds__(128) flash_tc()
{
    extern __shared__ float sm[];
    float (*Qs)[68] = reinterpret_cast<float(*)[68]>(sm);              // later Ps
    float (*Ks)[68] = reinterpret_cast<float(*)[68]>(sm + 64 * 68);
    float (*Vs)[68] = reinterpret_cast<float(*)[68]>(sm + 2 * 64 * 68);
    float (*Ps)[68] = Qs;  // Q staging buffer is dead after prologue

    const int tid  = threadIdx.x;
    const int wid  = tid >> 5;
    const int lane = tid & 31;
    const int g    = lane >> 2;
    const int tg   = lane & 3;
    const int bh = blockIdx.y;          // b*NH + h
    const int q0 = blockIdx.x << 6;

    const float* Qg = g_qkv + bh * (S_ * HD_);
    const float* Kg = g_qkv + PART + bh * (S_ * HD_);
    const float* Vg = g_qkv + 2 * PART + bh * (S_ * HD_);

    // ---- prologue: stage Q (scaled, tf32) and capture A-fragments ----
#pragma unroll
    for (int i = tid; i < 1024; i += 128) {
        const int r  = i >> 4;
        const int c4 = (i & 15) << 2;
        float4 v = *reinterpret_cast<const float4*>(Qg + (q0 + r) * HD_ + c4);
        Qs[r][c4 + 0] = tf32r(v.x * 0.125f);
        Qs[r][c4 + 1] = tf32r(v.y * 0.125f);
        Qs[r][c4 + 2] = tf32r(v.z * 0.125f);
        Qs[r][c4 + 3] = tf32r(v.w * 0.125f);
    }
    __syncthreads();

    const int qr = (wid << 4) + g;     // this thread's low row within tile
    uint32_t qa[8][4];
#pragma unroll
    for (int ks = 0; ks < 8; ++ks) {
        const int d0 = ks << 3;
        qa[ks][0] = __float_as_uint(Qs[qr    ][d0 + tg    ]);
        qa[ks][1] = __float_as_uint(Qs[qr + 8][d0 + tg    ]);
        qa[ks][2] = __float_as_uint(Qs[qr    ][d0 + tg + 4]);
        qa[ks][3] = __float_as_uint(Qs[qr + 8][d0 + tg + 4]);
    }

    float m_lo = -1e30f, m_hi = -1e30f, l_lo = 0.f, l_hi = 0.f;
    float O[8][4];
#pragma unroll
    for (int nt = 0; nt < 8; ++nt)
#pragma unroll
        for (int i = 0; i < 4; ++i) O[nt][i] = 0.f;

    for (int kt = 0; kt < S_; kt += 64) {
        __syncthreads();  // all warps done reading Ks/Vs/Ps of prior tile
        // ---- stage K, V tiles (tf32) ----
#pragma unroll
        for (int i = tid; i < 1024; i += 128) {
            const int r  = i >> 4;
            const int c4 = (i & 15) << 2;
            float4 kv = *reinterpret_cast<const float4*>(
                Kg + (kt + r) * HD_ + c4);
            Ks[r][c4 + 0] = tf32r(kv.x);
            Ks[r][c4 + 1] = tf32r(kv.y);
            Ks[r][c4 + 2] = tf32r(kv.z);
            Ks[r][c4 + 3] = tf32r(kv.w);
            float4 vv = *reinterpret_cast<const float4*>(
                Vg + (kt + r) * HD_ + c4);
            Vs[r][c4 + 0] = tf32r(vv.x);
            Vs[r][c4 + 1] = tf32r(vv.y);
            Vs[r][c4 + 2] = tf32r(vv.z);
            Vs[r][c4 + 3] = tf32r(vv.w);
        }
        __syncthreads();

        // ---- scores: S[16 x 64] per warp ----
        float c[8][4];
#pragma unroll
        for (int nt = 0; nt < 8; ++nt)
#pragma unroll
            for (int i = 0; i < 4; ++i) c[nt][i] = 0.f;
#pragma unroll
        for (int ks = 0; ks < 8; ++ks) {
            const int d0 = ks << 3;
#pragma unroll
            for (int nt = 0; nt < 8; ++nt) {
                const int key = (nt << 3) + g;
                const uint32_t b0 = __float_as_uint(Ks[key][d0 + tg    ]);
                const uint32_t b1 = __float_as_uint(Ks[key][d0 + tg + 4]);
                mma_tf32(c[nt], qa[ks], b0, b1);
            }
        }

        // ---- online softmax (rows qr and qr+8; quad = lanes sharing row) ----
        float mx0 = -1e30f, mx1 = -1e30f;
#pragma unroll
        for (int nt = 0; nt < 8; ++nt) {
            mx0 = fmaxf(mx0, fmaxf(c[nt][0], c[nt][1]));
            mx1 = fmaxf(mx1, fmaxf(c[nt][2], c[nt][3]));
        }
#pragma unroll
        for (int off = 1; off <= 2; off <<= 1) {
            mx0 = fmaxf(mx0, __shfl_xor_sync(0xffffffffu, mx0, off));
            mx1 = fmaxf(mx1, __shfl_xor_sync(0xffffffffu, mx1, off));
        }
        const float nm0 = fmaxf(m_lo, mx0);
        const float nm1 = fmaxf(m_hi, mx1);
        const float corr0 = __expf(m_lo - nm0);
        const float corr1 = __expf(m_hi - nm1);
        m_lo = nm0; m_hi = nm1;

        float rs0 = 0.f, rs1 = 0.f;
#pragma unroll
        for (int nt = 0; nt < 8; ++nt) {
            c[nt][0] = __expf(c[nt][0] - nm0);
            c[nt][1] = __expf(c[nt][1] - nm0);
            c[nt][2] = __expf(c[nt][2] - nm1);
            c[nt][3] = __expf(c[nt][3] - nm1);
            rs0 += c[nt][0] + c[nt][1];
            rs1 += c[nt][2] + c[nt][3];
        }
#pragma unroll
        for (int off = 1; off <= 2; off <<= 1) {
            rs0 += __shfl_xor_sync(0xffffffffu, rs0, off);
            rs1 += __shfl_xor_sync(0xffffffffu, rs1, off);
        }
        l_lo = l_lo * corr0 + rs0;
        l_hi = l_hi * corr1 + rs1;
#pragma unroll
        for (int nt = 0; nt < 8; ++nt) {
            O[nt][0] *= corr0;
            O[nt][1] *= corr0;
            O[nt][2] *= corr1;
            O[nt][3] *= corr1;
        }

        // ---- stage P (warp-private rows) as tf32 ----
#pragma unroll
        for (int nt = 0; nt < 8; ++nt) {
            const int col = (nt << 3) + (tg << 1);
            Ps[qr    ][col    ] = tf32r(c[nt][0]);
            Ps[qr    ][col + 1] = tf32r(c[nt][1]);
            Ps[qr + 8][col    ] = tf32r(c[nt][2]);
            Ps[qr + 8][col + 1] = tf32r(c[nt][3]);
        }
        __syncwarp();

        // ---- PV: O[16 x 64] += P[16 x 64] @ V[64 x 64] ----
#pragma unroll
        for (int ks = 0; ks < 8; ++ks) {
            const int k0 = ks << 3;
            uint32_t pa[4];
            pa[0] = __float_as_uint(Ps[qr    ][k0 + tg    ]);
            pa[1] = __float_as_uint(Ps[qr + 8][k0 + tg    ]);
            pa[2] = __float_as_uint(Ps[qr    ][k0 + tg + 4]);
            pa[3] = __float_as_uint(Ps[qr + 8][k0 + tg + 4]);
#pragma unroll
            for (int nt = 0; nt < 8; ++nt) {
                const int n0 = (nt << 3) + g;
                const uint32_t b0 = __float_as_uint(Vs[k0 + tg    ][n0]);
                const uint32_t b1 = __float_as_uint(Vs[k0 + tg + 4][n0]);
                mma_tf32(O[nt], pa, b0, b1);
            }
        }
    }

    // ---- epilogue: normalize, write g_att [B,S,H,HD] ----
    const float inv_lo = 1.f / l_lo;
    const float inv_hi = 1.f / l_hi;
    const int bb = bh >> 4;
    const int h  = bh & 15;
    const long base_lo = (((long)(bb * S_ + q0 + qr)     * NH_ + h)) * HD_;
    const long base_hi = (((long)(bb * S_ + q0 + qr + 8) * NH_ + h)) * HD_;
#pragma unroll
    for (int nt = 0; nt < 8; ++nt) {
        const int col = (nt << 3) + (tg << 1);
        float2 vlo, vhi;
        vlo.x = O[nt][0] * inv_lo;
        vlo.y = O[nt][1] * inv_lo;
        vhi.x = O[nt][2] * inv_hi;
        vhi.y = O[nt][3] * inv_hi;
        *reinterpret_cast<float2*>(g_att + base_lo + col) = vlo;
        *reinterpret_cast<float2*>(g_att + base_hi + col) = vhi;
    }
}

// ---------------------------------------------------------------------------
extern "C" void kernel_launch(void* const* d_in, const int* in_sizes, int n_in,
                              void* d_out, int out_size)
{
    (void)in_sizes; (void)n_in; (void)out_size;
    const float* x     = (const float*)d_in[0];
    const float* w_qkv = (const float*)d_in[1];
    const float* b_qkv = (const float*)d_in[2];
    const float* w_out = (const float*)d_in[3];
    const float* b_out = (const float*)d_in[4];
    float* out = (float*)d_out;

    cudaFuncSetAttribute(flash_tc,
                         cudaFuncAttributeMaxDynamicSharedMemorySize, FLASH_SMEM);

    // 1) QKV GEMM + bias + scatter: [8192,1024] @ [1024,3072]
    gemm_tc<0><<<dim3((3 * D_) / 128, MROWS / 128), 256>>>(
        x, w_qkv, b_qkv, nullptr, D_, 3 * D_);

    // 2) Flash attention over all (b,h) and query tiles
    flash_tc<<<dim3(S_ / 64, B_ * NH_), 128, FLASH_SMEM>>>();

    // 3) Output projection: [8192,1024] @ [1024,1024] + bias -> d_out
    gemm_tc<1><<<dim3(D_ / 128, MROWS / 128), 256>>>(
        nullptr, w_out, b_out, out, D_, D_);
}

// round 8
// speedup vs baseline: 3.3349x; 1.1636x over previous
#include <cuda_runtime.h>
#include <cstdint>

// Problem constants: B=4, S=2048, D=1024, H=16, HD=64
namespace {
constexpr int B_  = 4;
constexpr int S_  = 2048;
constexpr int D_  = 1024;
constexpr int NH_ = 16;
constexpr int HD_ = 64;
constexpr int MROWS = B_ * S_;              // 8192
constexpr int PART  = B_ * NH_ * S_ * HD_;  // 8,388,608 elems per Q/K/V part
// Flash smem: Ps[128][68] (doubles as Q staging), Ks[64][68], Vs[64][68]
constexpr int FLASH_SMEM = (128 + 64 + 64) * 68 * 4;  // 69,632 bytes
}

// Scratch (static device globals: allowed; runtime allocation is not)
__device__ float g_qkv[3 * PART];       // [3][B,H,S,HD]
__device__ float g_att[B_ * S_ * D_];   // [B,S,H,HD] == [B,S,D]

// ---------------------------------------------------------------------------
// helpers: tf32 convert (round-to-nearest) + m16n8k8 tf32 MMA
// ---------------------------------------------------------------------------
__device__ __forceinline__ float tf32r(float x) {
    uint32_t u;
    asm("cvt.rna.tf32.f32 %0, %1;" : "=r"(u) : "f"(x));
    return __uint_as_float(u);
}

__device__ __forceinline__ void mma_tf32(float c[4], const uint32_t a[4],
                                         uint32_t b0, uint32_t b1) {
    asm volatile(
        "mma.sync.aligned.m16n8k8.row.col.f32.tf32.tf32.f32 "
        "{%0,%1,%2,%3}, {%4,%5,%6,%7}, {%8,%9}, {%0,%1,%2,%3};"
        : "+f"(c[0]), "+f"(c[1]), "+f"(c[2]), "+f"(c[3])
        : "r"(a[0]), "r"(a[1]), "r"(a[2]), "r"(a[3]), "r"(b0), "r"(b1));
}

// ---------------------------------------------------------------------------
// TF32 tensor-core GEMM: C[M,N] = A[M,K] @ W[K,N] + bias[N]
//   128x128 block tile, BK=16, 128 threads = 4 warps in 2x2,
//   each warp 64x64 via 4x8 grid of m16n8k8. Global->reg prefetch of the
//   next k-tile overlaps LDG latency with the MMA loop.
//   MODE 0: A = Ain (x), epilogue scatters into g_qkv [3][B,H,S,HD]
//   MODE 1: A = g_att, epilogue writes Cout[M,N] directly
// ---------------------------------------------------------------------------
template <int MODE>
__global__ void __launch_bounds__(128) gemm_tc(
    const float* __restrict__ Ain, const float* __restrict__ Wm,
    const float* __restrict__ bias, float* __restrict__ Cout,
    int K, int N)
{
    __shared__ float As[128][20];   // pad 16->20: conflict-free A frag loads
    __shared__ float Bs[16][132];   // pad 128->132: conflict-free B frag loads

    const int tid  = threadIdx.x;
    const int wid  = tid >> 5;
    const int lane = tid & 31;
    const int g    = lane >> 2;   // row within fragment
    const int tg   = lane & 3;    // col within fragment
    const int warp_m = wid >> 1;  // 0..1 -> m offset *64
    const int warp_n = wid & 1;   // 0..1 -> n offset *64
    const int m0 = blockIdx.y << 7;
    const int n0 = blockIdx.x << 7;

    const float* A = (MODE == 0) ? Ain : g_att;

    float c[4][8][4];
#pragma unroll
    for (int mt = 0; mt < 4; ++mt)
#pragma unroll
        for (int nt = 0; nt < 8; ++nt)
#pragma unroll
            for (int i = 0; i < 4; ++i) c[mt][nt][i] = 0.f;

    // staging assignments: A tile 128x16 = 512 float4; B tile 16x128 = 512 float4
    float4 pa[4], pb[4];
#pragma unroll
    for (int j = 0; j < 4; ++j) {
        const int i  = tid + (j << 7);
        const int ar = i >> 2,  ac = (i & 3) << 2;
        const int br = i >> 5,  bc = (i & 31) << 2;
        pa[j] = *reinterpret_cast<const float4*>(A + (m0 + ar) * K + ac);
        pb[j] = *reinterpret_cast<const float4*>(Wm + br * N + n0 + bc);
    }

    for (int k0 = 0; k0 < K; k0 += 16) {
        // write prefetched tile to smem (tf32-rounded)
#pragma unroll
        for (int j = 0; j < 4; ++j) {
            const int i  = tid + (j << 7);
            const int ar = i >> 2,  ac = (i & 3) << 2;
            const int br = i >> 5,  bc = (i & 31) << 2;
            As[ar][ac + 0] = tf32r(pa[j].x);
            As[ar][ac + 1] = tf32r(pa[j].y);
            As[ar][ac + 2] = tf32r(pa[j].z);
            As[ar][ac + 3] = tf32r(pa[j].w);
            Bs[br][bc + 0] = tf32r(pb[j].x);
            Bs[br][bc + 1] = tf32r(pb[j].y);
            Bs[br][bc + 2] = tf32r(pb[j].z);
            Bs[br][bc + 3] = tf32r(pb[j].w);
        }
        __syncthreads();

        // prefetch next k-tile (LDG latency overlaps the MMA loop below)
        if (k0 + 16 < K) {
#pragma unroll
            for (int j = 0; j < 4; ++j) {
                const int i  = tid + (j << 7);
                const int ar = i >> 2,  ac = (i & 3) << 2;
                const int br = i >> 5,  bc = (i & 31) << 2;
                pa[j] = *reinterpret_cast<const float4*>(
                    A + (m0 + ar) * K + k0 + 16 + ac);
                pb[j] = *reinterpret_cast<const float4*>(
                    Wm + (k0 + 16 + br) * N + n0 + bc);
            }
        }

#pragma unroll
        for (int kk = 0; kk < 16; kk += 8) {
            uint32_t a[4][4], b[8][2];
#pragma unroll
            for (int mt = 0; mt < 4; ++mt) {
                const int r = (warp_m << 6) + (mt << 4) + g;
                a[mt][0] = __float_as_uint(As[r    ][kk + tg    ]);
                a[mt][1] = __float_as_uint(As[r + 8][kk + tg    ]);
                a[mt][2] = __float_as_uint(As[r    ][kk + tg + 4]);
                a[mt][3] = __float_as_uint(As[r + 8][kk + tg + 4]);
            }
#pragma unroll
            for (int nt = 0; nt < 8; ++nt) {
                const int cn = (warp_n << 6) + (nt << 3) + g;
                b[nt][0] = __float_as_uint(Bs[kk + tg    ][cn]);
                b[nt][1] = __float_as_uint(Bs[kk + tg + 4][cn]);
            }
#pragma unroll
            for (int mt = 0; mt < 4; ++mt)
#pragma unroll
                for (int nt = 0; nt < 8; ++nt)
                    mma_tf32(c[mt][nt], a[mt], b[nt][0], b[nt][1]);
        }
        __syncthreads();
    }

    // epilogue: C fragment (rows g/g+8, cols 2*tg, 2*tg+1) + bias
#pragma unroll
    for (int nt = 0; nt < 8; ++nt) {
        const int col = n0 + (warp_n << 6) + (nt << 3) + (tg << 1);
        const float2 b2 = *reinterpret_cast<const float2*>(bias + col);
#pragma unroll
        for (int mt = 0; mt < 4; ++mt) {
            const int r_lo = m0 + (warp_m << 6) + (mt << 4) + g;
            float2 vlo, vhi;
            vlo.x = c[mt][nt][0] + b2.x;
            vlo.y = c[mt][nt][1] + b2.y;
            vhi.x = c[mt][nt][2] + b2.x;
            vhi.y = c[mt][nt][3] + b2.y;
            if (MODE == 0) {
                const int part = col >> 10;
                const int rem  = col & 1023;
                const int h    = rem >> 6;
                const int hd0  = rem & 63;
                float* dst = g_qkv + part * PART;
                {
                    const int m  = r_lo;
                    const int bb = m >> 11, ss = m & 2047;
                    *reinterpret_cast<float2*>(
                        dst + ((bb * NH_ + h) * S_ + ss) * HD_ + hd0) = vlo;
                }
                {
                    const int m  = r_lo + 8;
                    const int bb = m >> 11, ss = m & 2047;
                    *reinterpret_cast<float2*>(
                        dst + ((bb * NH_ + h) * S_ + ss) * HD_ + hd0) = vhi;
                }
            } else {
                *reinterpret_cast<float2*>(Cout + r_lo * N + col) = vlo;
                *reinterpret_cast<float2*>(Cout + (r_lo + 8) * N + col) = vhi;
            }
        }
    }
}

// ---------------------------------------------------------------------------
// Flash attention, tf32 tensor cores, HD=64.
//   Grid: (S/128 query tiles, B*H). 128 threads = 4 warps; warp w owns
//   query rows [w*32, w*32+32) -> 2 row-blocks of 16 (mt=0,1), so every
//   K/V fragment load feeds 2 MMAs. Q persistent in registers (scaled).
//   P restaged through its warp-private rows of Ps (the dead Q buffer).
// ---------------------------------------------------------------------------
__global__ void __launch_bounds__(128) flash_tc()
{
    extern __shared__ float sm[];
    float (*Ps)[68] = reinterpret_cast<float(*)[68]>(sm);            // [128][68]
    float (*Ks)[68] = reinterpret_cast<float(*)[68]>(sm + 128 * 68); // [64][68]
    float (*Vs)[68] = reinterpret_cast<float(*)[68]>(sm + 192 * 68); // [64][68]

    const int tid  = threadIdx.x;
    const int wid  = tid >> 5;
    const int lane = tid & 31;
    const int g    = lane >> 2;
    const int tg   = lane & 3;
    const int bh = blockIdx.y;          // b*NH + h
    const int q0 = blockIdx.x << 7;     // 128 query rows per block

    const float* Qg = g_qkv + bh * (S_ * HD_);
    const float* Kg = g_qkv + PART + bh * (S_ * HD_);
    const float* Vg = g_qkv + 2 * PART + bh * (S_ * HD_);

    // ---- prologue: stage Q (scaled, tf32) then capture A-fragments ----
#pragma unroll
    for (int i = tid; i < 2048; i += 128) {
        const int r  = i >> 4;
        const int c4 = (i & 15) << 2;
        float4 v = *reinterpret_cast<const float4*>(Qg + (q0 + r) * HD_ + c4);
        Ps[r][c4 + 0] = tf32r(v.x * 0.125f);
        Ps[r][c4 + 1] = tf32r(v.y * 0.125f);
        Ps[r][c4 + 2] = tf32r(v.z * 0.125f);
        Ps[r][c4 + 3] = tf32r(v.w * 0.125f);
    }
    __syncthreads();

    const int qrw = wid << 5;  // warp's base query row within tile
    uint32_t qa[2][8][4];
#pragma unroll
    for (int mt = 0; mt < 2; ++mt) {
        const int r = qrw + (mt << 4) + g;
#pragma unroll
        for (int ks = 0; ks < 8; ++ks) {
            const int d0 = ks << 3;
            qa[mt][ks][0] = __float_as_uint(Ps[r    ][d0 + tg    ]);
            qa[mt][ks][1] = __float_as_uint(Ps[r + 8][d0 + tg    ]);
            qa[mt][ks][2] = __float_as_uint(Ps[r    ][d0 + tg + 4]);
            qa[mt][ks][3] = __float_as_uint(Ps[r + 8][d0 + tg + 4]);
        }
    }

    float m_[2][2], l_[2][2], O[2][8][4];
#pragma unroll
    for (int mt = 0; mt < 2; ++mt) {
        m_[mt][0] = -1e30f; m_[mt][1] = -1e30f;
        l_[mt][0] = 0.f;    l_[mt][1] = 0.f;
#pragma unroll
        for (int nt = 0; nt < 8; ++nt)
#pragma unroll
            for (int i = 0; i < 4; ++i) O[mt][nt][i] = 0.f;
    }

    for (int kt = 0; kt < S_; kt += 64) {
        __syncthreads();  // all warps done reading Ks/Vs of prior tile
        // ---- stage K, V tiles (tf32) ----
#pragma unroll
        for (int i = tid; i < 1024; i += 128) {
            const int r  = i >> 4;
            const int c4 = (i & 15) << 2;
            float4 kv = *reinterpret_cast<const float4*>(
                Kg + (kt + r) * HD_ + c4);
            Ks[r][c4 + 0] = tf32r(kv.x);
            Ks[r][c4 + 1] = tf32r(kv.y);
            Ks[r][c4 + 2] = tf32r(kv.z);
            Ks[r][c4 + 3] = tf32r(kv.w);
            float4 vv = *reinterpret_cast<const float4*>(
                Vg + (kt + r) * HD_ + c4);
            Vs[r][c4 + 0] = tf32r(vv.x);
            Vs[r][c4 + 1] = tf32r(vv.y);
            Vs[r][c4 + 2] = tf32r(vv.z);
            Vs[r][c4 + 3] = tf32r(vv.w);
        }
        __syncthreads();

        // ---- scores: S[32 x 64] per warp; each K frag feeds 2 MMAs ----
        float c[2][8][4];
#pragma unroll
        for (int mt = 0; mt < 2; ++mt)
#pragma unroll
            for (int nt = 0; nt < 8; ++nt)
#pragma unroll
                for (int i = 0; i < 4; ++i) c[mt][nt][i] = 0.f;
#pragma unroll
        for (int ks = 0; ks < 8; ++ks) {
            const int d0 = ks << 3;
#pragma unroll
            for (int nt = 0; nt < 8; ++nt) {
                const int key = (nt << 3) + g;
                const uint32_t b0 = __float_as_uint(Ks[key][d0 + tg    ]);
                const uint32_t b1 = __float_as_uint(Ks[key][d0 + tg + 4]);
                mma_tf32(c[0][nt], qa[0][ks], b0, b1);
                mma_tf32(c[1][nt], qa[1][ks], b0, b1);
            }
        }

        // ---- online softmax + stage P (per row-block) ----
#pragma unroll
        for (int mt = 0; mt < 2; ++mt) {
            float mx0 = -1e30f, mx1 = -1e30f;
#pragma unroll
            for (int nt = 0; nt < 8; ++nt) {
                mx0 = fmaxf(mx0, fmaxf(c[mt][nt][0], c[mt][nt][1]));
                mx1 = fmaxf(mx1, fmaxf(c[mt][nt][2], c[mt][nt][3]));
            }
#pragma unroll
            for (int off = 1; off <= 2; off <<= 1) {
                mx0 = fmaxf(mx0, __shfl_xor_sync(0xffffffffu, mx0, off));
                mx1 = fmaxf(mx1, __shfl_xor_sync(0xffffffffu, mx1, off));
            }
            const float nm0 = fmaxf(m_[mt][0], mx0);
            const float nm1 = fmaxf(m_[mt][1], mx1);
            const float corr0 = __expf(m_[mt][0] - nm0);
            const float corr1 = __expf(m_[mt][1] - nm1);
            m_[mt][0] = nm0; m_[mt][1] = nm1;

            float rs0 = 0.f, rs1 = 0.f;
#pragma unroll
            for (int nt = 0; nt < 8; ++nt) {
                c[mt][nt][0] = __expf(c[mt][nt][0] - nm0);
                c[mt][nt][1] = __expf(c[mt][nt][1] - nm0);
                c[mt][nt][2] = __expf(c[mt][nt][2] - nm1);
                c[mt][nt][3] = __expf(c[mt][nt][3] - nm1);
                rs0 += c[mt][nt][0] + c[mt][nt][1];
                rs1 += c[mt][nt][2] + c[mt][nt][3];
            }
#pragma unroll
            for (int off = 1; off <= 2; off <<= 1) {
                rs0 += __shfl_xor_sync(0xffffffffu, rs0, off);
                rs1 += __shfl_xor_sync(0xffffffffu, rs1, off);
            }
            l_[mt][0] = l_[mt][0] * corr0 + rs0;
            l_[mt][1] = l_[mt][1] * corr1 + rs1;
#pragma unroll
            for (int nt = 0; nt < 8; ++nt) {
                O[mt][nt][0] *= corr0;
                O[mt][nt][1] *= corr0;
                O[mt][nt][2] *= corr1;
                O[mt][nt][3] *= corr1;
            }
            // stage P (warp-private rows) as tf32
            const int row = qrw + (mt << 4) + g;
#pragma unroll
            for (int nt = 0; nt < 8; ++nt) {
                const int col = (nt << 3) + (tg << 1);
                float2 plo, phi;
                plo.x = tf32r(c[mt][nt][0]);
                plo.y = tf32r(c[mt][nt][1]);
                phi.x = tf32r(c[mt][nt][2]);
                phi.y = tf32r(c[mt][nt][3]);
                *reinterpret_cast<float2*>(&Ps[row    ][col]) = plo;
                *reinterpret_cast<float2*>(&Ps[row + 8][col]) = phi;
            }
        }
        __syncwarp();

        // ---- PV: O[32 x 64] += P[32 x 64] @ V[64 x 64] ----
#pragma unroll
        for (int ks = 0; ks < 8; ++ks) {
            const int k0 = ks << 3;
            uint32_t pa0[4], pa1[4];
            const int r0 = qrw + g;
            const int r1 = qrw + 16 + g;
            pa0[0] = __float_as_uint(Ps[r0    ][k0 + tg    ]);
            pa0[1] = __float_as_uint(Ps[r0 + 8][k0 + tg    ]);
            pa0[2] = __float_as_uint(Ps[r0    ][k0 + tg + 4]);
            pa0[3] = __float_as_uint(Ps[r0 + 8][k0 + tg + 4]);
            pa1[0] = __float_as_uint(Ps[r1    ][k0 + tg    ]);
            pa1[1] = __float_as_uint(Ps[r1 + 8][k0 + tg    ]);
            pa1[2] = __float_as_uint(Ps[r1    ][k0 + tg + 4]);
            pa1[3] = __float_as_uint(Ps[r1 + 8][k0 + tg + 4]);
#pragma unroll
            for (int nt = 0; nt < 8; ++nt) {
                const int nn = (nt << 3) + g;
                const uint32_t b0 = __float_as_uint(Vs[k0 + tg    ][nn]);
                const uint32_t b1 = __float_as_uint(Vs[k0 + tg + 4][nn]);
                mma_tf32(O[0][nt], pa0, b0, b1);
                mma_tf32(O[1][nt], pa1, b0, b1);
            }
        }
    }

    // ---- epilogue: normalize, write g_att [B,S,H,HD] ----
    const int bb = bh >> 4;
    const int h  = bh & 15;
#pragma unroll
    for (int mt = 0; mt < 2; ++mt) {
        const float inv0 = 1.f / l_[mt][0];
        const float inv1 = 1.f / l_[mt][1];
        const int row = q0 + qrw + (mt << 4) + g;
        const long base_lo = ((long)(bb * S_ + row)     * NH_ + h) * HD_;
        const long base_hi = ((long)(bb * S_ + row + 8) * NH_ + h) * HD_;
#pragma unroll
        for (int nt = 0; nt < 8; ++nt) {
            const int col = (nt << 3) + (tg << 1);
            float2 vlo, vhi;
            vlo.x = O[mt][nt][0] * inv0;
            vlo.y = O[mt][nt][1] * inv0;
            vhi.x = O[mt][nt][2] * inv1;
            vhi.y = O[mt][nt][3] * inv1;
            *reinterpret_cast<float2*>(g_att + base_lo + col) = vlo;
            *reinterpret_cast<float2*>(g_att + base_hi + col) = vhi;
        }
    }
}

// ---------------------------------------------------------------------------
extern "C" void kernel_launch(void* const* d_in, const int* in_sizes, int n_in,
                              void* d_out, int out_size)
{
    (void)in_sizes; (void)n_in; (void)out_size;
    const float* x     = (const float*)d_in[0];
    const float* w_qkv = (const float*)d_in[1];
    const float* b_qkv = (const float*)d_in[2];
    const float* w_out = (const float*)d_in[3];
    const float* b_out = (const float*)d_in[4];
    float* out = (float*)d_out;

    cudaFuncSetAttribute(flash_tc,
                         cudaFuncAttributeMaxDynamicSharedMemorySize, FLASH_SMEM);

    // 1) QKV GEMM + bias + scatter: [8192,1024] @ [1024,3072]
    gemm_tc<0><<<dim3((3 * D_) / 128, MROWS / 128), 128>>>(
        x, w_qkv, b_qkv, nullptr, D_, 3 * D_);

    // 2) Flash attention over all (b,h) and query tiles
    flash_tc<<<dim3(S_ / 128, B_ * NH_), 128, FLASH_SMEM>>>();

    // 3) Output projection: [8192,1024] @ [1024,1024] + bias -> d_out
    gemm_tc<1><<<dim3(D_ / 128, MROWS / 128), 128>>>(
        nullptr, w_out, b_out, out, D_, D_);
}